// round 1
// baseline (speedup 1.0000x reference)
#include <cuda_runtime.h>
#include <math.h>

// ---------------------------------------------------------------------------
// Multi-scale morphological closing, [4,8,256,256] -> [4,8,4,256,256]
// closing_k = Verode(Herode(Vdilate(Hdilate(x)))) with parabolic SE, scale t_k=4^k,
// half-width W_k = 4*sqrt(t_k) in {4,8,16,32}, se_j = (j-W)^2 * 4/W^2 (exact fp32).
// Candidate = fmaf(coef, -se_j, x) (dilate) / fmaf(coef, +se_j, x) (erode).
// 4 kernels (one per pass), all 4 scales fused via blockIdx.z.
// ---------------------------------------------------------------------------

static constexpr int IMG_H = 256;
static constexpr int IMG_W = 256;
static constexpr int NIMG  = 32;                 // B*C = 4*8
static constexpr int NSC   = 4;
static constexpr size_t IMG_SZ = (size_t)IMG_H * IMG_W;      // 65536
static constexpr size_t SLAB   = (size_t)NIMG * IMG_SZ;      // 2,097,152 floats
static constexpr float PADV = 10000.0f;
static constexpr int T = 8;                      // outputs per thread along pass axis

// scratch (allocation-free: device globals)
__device__ float g_s1[NSC * SLAB];               // 32 MB
__device__ float g_s2[NSC * SLAB];               // 32 MB

template <int W>
__device__ __forceinline__ constexpr float se_val(int j) {
    // (1/(4t)) * (j-W)^2 with t = (W/4)^2  ->  (j-W)^2 * 4/(W*W); exact in fp32.
    return (float)((j - W) * (j - W)) * (4.0f / (float)(W * W));
}

// ---------------- horizontal pass: contiguous along W ----------------
template <int W, bool ISMAX>
__device__ __forceinline__ void hpass(const float* __restrict__ src,
                                      float* __restrict__ dst, float coef)
{
    unsigned g    = blockIdx.x * 256u + threadIdx.x;   // 0 .. 262143
    unsigned rowg = g >> 5;                            // global row (32 groups/row, T=8)
    unsigned p0   = (g & 31u) * T;
    const float* row = src + rowg * (unsigned)IMG_W;

    float xbuf[T + 2 * W];
#pragma unroll
    for (int m = 0; m < T + 2 * W; m++) {
        int idx = (int)p0 - W + m;
        float v = ISMAX ? -PADV : PADV;
        if (idx >= 0 && idx < IMG_W) v = __ldg(row + idx);
        xbuf[m] = v;
    }

    float acc[T];
#pragma unroll
    for (int i = 0; i < T; i++) acc[i] = ISMAX ? -INFINITY : INFINITY;

#pragma unroll
    for (int j = 0; j <= 2 * W; j++) {
        const float se = ISMAX ? -se_val<W>(j) : se_val<W>(j);
#pragma unroll
        for (int i = 0; i < T; i++) {
            float cand = fmaf(coef, se, xbuf[i + j]);   // FFMA-imm (se is a literal)
            acc[i] = ISMAX ? fmaxf(acc[i], cand) : fminf(acc[i], cand);
        }
    }

    float4* o = reinterpret_cast<float4*>(dst + rowg * (unsigned)IMG_W + p0);
    o[0] = make_float4(acc[0], acc[1], acc[2], acc[3]);
    o[1] = make_float4(acc[4], acc[5], acc[6], acc[7]);
}

// ---------------- vertical pass: stride IMG_W along H ----------------
template <int W, bool ISMAX>
__device__ __forceinline__ void vpass(const float* __restrict__ src,
                                      float* __restrict__ dst, float coef,
                                      unsigned dstImgStride)
{
    unsigned g      = blockIdx.x * 256u + threadIdx.x;  // 0 .. 262143
    unsigned col    = g & 255u;
    unsigned rowgrp = (g >> 8) & 31u;                   // 256/T = 32 row groups
    unsigned img    = g >> 13;                          // 0 .. 31
    int r0 = (int)(rowgrp * T);
    const float* s = src + img * (unsigned)IMG_SZ + col;

    float xbuf[T + 2 * W];
#pragma unroll
    for (int m = 0; m < T + 2 * W; m++) {
        int r = r0 - W + m;
        float v = ISMAX ? -PADV : PADV;
        if (r >= 0 && r < IMG_H) v = __ldg(s + r * IMG_W);
        xbuf[m] = v;
    }

    float acc[T];
#pragma unroll
    for (int i = 0; i < T; i++) acc[i] = ISMAX ? -INFINITY : INFINITY;

#pragma unroll
    for (int j = 0; j <= 2 * W; j++) {
        const float se = ISMAX ? -se_val<W>(j) : se_val<W>(j);
#pragma unroll
        for (int i = 0; i < T; i++) {
            float cand = fmaf(coef, se, xbuf[i + j]);
            acc[i] = ISMAX ? fmaxf(acc[i], cand) : fminf(acc[i], cand);
        }
    }

    float* d = dst + img * dstImgStride + (unsigned)r0 * IMG_W + col;
#pragma unroll
    for (int i = 0; i < T; i++) d[i * IMG_W] = acc[i];
}

// ---------------- pass kernels (scale = blockIdx.z) ----------------
__global__ void __launch_bounds__(256, 2)
k_pass1(const float* __restrict__ in, const float* __restrict__ coefp)
{
    float coef = __ldg(coefp);
    unsigned sc = blockIdx.z;
    float* dp = g_s1 + (size_t)sc * SLAB;
    switch (sc) {
        case 0:  hpass<4,  true>(in, dp, coef); break;
        case 1:  hpass<8,  true>(in, dp, coef); break;
        case 2:  hpass<16, true>(in, dp, coef); break;
        default: hpass<32, true>(in, dp, coef); break;
    }
}

__global__ void __launch_bounds__(256, 2)
k_pass2(const float* __restrict__ coefp)
{
    float coef = __ldg(coefp);
    unsigned sc = blockIdx.z;
    const float* sp = g_s1 + (size_t)sc * SLAB;
    float* dp = g_s2 + (size_t)sc * SLAB;
    switch (sc) {
        case 0:  vpass<4,  true>(sp, dp, coef, (unsigned)IMG_SZ); break;
        case 1:  vpass<8,  true>(sp, dp, coef, (unsigned)IMG_SZ); break;
        case 2:  vpass<16, true>(sp, dp, coef, (unsigned)IMG_SZ); break;
        default: vpass<32, true>(sp, dp, coef, (unsigned)IMG_SZ); break;
    }
}

__global__ void __launch_bounds__(256, 2)
k_pass3(const float* __restrict__ coefp)
{
    float coef = __ldg(coefp);
    unsigned sc = blockIdx.z;
    const float* sp = g_s2 + (size_t)sc * SLAB;
    float* dp = g_s1 + (size_t)sc * SLAB;
    switch (sc) {
        case 0:  hpass<4,  false>(sp, dp, coef); break;
        case 1:  hpass<8,  false>(sp, dp, coef); break;
        case 2:  hpass<16, false>(sp, dp, coef); break;
        default: hpass<32, false>(sp, dp, coef); break;
    }
}

__global__ void __launch_bounds__(256, 2)
k_pass4(float* __restrict__ out, const float* __restrict__ coefp)
{
    float coef = __ldg(coefp);
    unsigned sc = blockIdx.z;
    const float* sp = g_s1 + (size_t)sc * SLAB;
    // out layout: [img][scale][H][W]  -> scale stride IMG_SZ, img stride NSC*IMG_SZ
    float* dp = out + (size_t)sc * IMG_SZ;
    const unsigned imgStride = (unsigned)(NSC * IMG_SZ);
    switch (sc) {
        case 0:  vpass<4,  false>(sp, dp, coef, imgStride); break;
        case 1:  vpass<8,  false>(sp, dp, coef, imgStride); break;
        case 2:  vpass<16, false>(sp, dp, coef, imgStride); break;
        default: vpass<32, false>(sp, dp, coef, imgStride); break;
    }
}

extern "C" void kernel_launch(void* const* d_in, const int* in_sizes, int n_in,
                              void* d_out, int out_size)
{
    const float* in   = (const float*)d_in[0];
    const float* coef = (const float*)d_in[1];
    float* out        = (float*)d_out;

    // 262144 threads per scale-slice: 1024 blocks x 256 threads, z = scale
    dim3 grid(1024, 1, NSC);
    dim3 block(256, 1, 1);

    k_pass1<<<grid, block>>>(in, coef);     // H dilate: in   -> s1
    k_pass2<<<grid, block>>>(coef);         // V dilate: s1   -> s2
    k_pass3<<<grid, block>>>(coef);         // H erode : s2   -> s1
    k_pass4<<<grid, block>>>(out, coef);    // V erode : s1   -> out
}

// round 2
// speedup vs baseline: 1.4617x; 1.4617x over previous
#include <cuda_runtime.h>
#include <math.h>

// ---------------------------------------------------------------------------
// Multi-scale morphological closing, [4,8,256,256] -> [4,8,4,256,256]
// Per scale k: Verode(Herode(Vdil(Hdil(x)))), parabolic SE, W_k in {4,8,16,32},
// se(x) = x^2 * 4/W^2 (exact fp32), candidate = fmaf(coef, -/+se, v).
// Padded scratch (stride 320, 32-halo filled with +/-PADV) -> no predicates,
// pure LDG.128 / FFMA-imm / FMNMX inner loops. Rolling accumulation (no big
// register window). V passes vectorized x4 columns.
// ---------------------------------------------------------------------------

static constexpr float PADV = 10000.0f;
static constexpr unsigned PSTR  = 320;                 // padded row stride (floats)
static constexpr size_t   PIMG  = 320u * 320u;         // padded image (102400)
static constexpr size_t   PSLAB = PIMG * 32u;          // per-scale slab (32 imgs)
static constexpr size_t   INIMG = 320u * 256u;         // in_pad image (81920)

__device__ float g_inpad[INIMG * 32];                  // 10.5 MB
__device__ float g_s1[PSLAB * 4];                      // 52.4 MB
__device__ float g_s2[PSLAB * 4];                      // 52.4 MB
__device__ float g_s3[PSLAB * 4];                      // 52.4 MB

template <int W>
__device__ __forceinline__ constexpr float sew(int x) {
    return (float)(x * x) * (4.0f / (float)(W * W));   // exact fp32 (4/W^2 = 2^-m)
}

// ---------------- prep: build padded input + constant halos ----------------
__global__ void __launch_bounds__(256) k_prep(const float* __restrict__ in)
{
    unsigned f = blockIdx.x * 256u + threadIdx.x;
    unsigned task = blockIdx.y;
    const float4 neg = make_float4(-PADV, -PADV, -PADV, -PADV);
    const float4 pos = make_float4( PADV,  PADV,  PADV,  PADV);

    if (task == 0) {                    // in_pad: copy interior, -PADV col halo
        if (f >= 655360u) return;       // 32 imgs * 256 rows * 80 f4
        unsigned img = f / 20480u, rem = f % 20480u;
        unsigned row = rem / 80u, c4 = rem % 80u;
        float4* d = reinterpret_cast<float4*>(g_inpad) + img * 20480u + row * 80u + c4;
        if (c4 >= 8u && c4 < 72u) {
            const float4* s = reinterpret_cast<const float4*>(in)
                              + img * 16384u + row * 64u + (c4 - 8u);
            *d = __ldg(s);
        } else {
            *d = neg;
        }
    } else if (task == 1u || task == 3u) {   // s1 (-PADV) / s3 (+PADV) row halos
        if (f >= 655360u) return;            // 128 img-scales * 64 rows * 80 f4
        unsigned imgsc = f / 5120u, rem = f % 5120u;
        unsigned rowIdx = rem / 80u, c4 = rem % 80u;
        unsigned row = (rowIdx < 32u) ? rowIdx : (256u + rowIdx);
        float* buf = (task == 1u) ? g_s1 : g_s3;
        float4* d = reinterpret_cast<float4*>(buf) + imgsc * 25600u + row * 80u + c4;
        *d = (task == 1u) ? neg : pos;
    } else {                                 // s2 (+PADV) col halos
        if (f >= 524288u) return;            // 128 img-scales * 256 rows * 16 f4
        unsigned imgsc = f / 4096u, rem = f % 4096u;
        unsigned row = rem / 16u, k = rem % 16u;
        unsigned c4 = (k < 8u) ? k : (64u + k);
        float4* d = reinterpret_cast<float4*>(g_s2) + imgsc * 25600u + (32u + row) * 80u + c4;
        *d = pos;
    }
}

// ---------------- horizontal pass: T contiguous outputs per thread ----------
template <int W, int T, bool ISMAX>
__device__ __forceinline__ void hscale(unsigned t, const float* __restrict__ src,
                                       unsigned srcImgStride, unsigned srcRowOff,
                                       float* __restrict__ dst, float coef)
{
    constexpr unsigned NG = 256 / T;
    unsigned row = t / NG, grp = t % NG;
    unsigned p0 = grp * T;
    unsigned img = row >> 8, r = row & 255u;
    const float* s = src + (size_t)img * srcImgStride
                         + (size_t)(srcRowOff + r) * PSTR + 32u + p0 - W;

    float acc[T];
    constexpr int NLD = (T + 2 * W) / 4;
#pragma unroll
    for (int v = 0; v < NLD; v++) {
        float4 q = __ldg(reinterpret_cast<const float4*>(s) + v);
        float qa[4] = {q.x, q.y, q.z, q.w};
#pragma unroll
        for (int c = 0; c < 4; c++) {
            int m = 4 * v + c;
#pragma unroll
            for (int i = 0; i < T; i++) {
                if (m >= i && m <= i + 2 * W) {
                    float wv = ISMAX ? -sew<W>(m - W - i) : sew<W>(m - W - i);
                    float cand = fmaf(coef, wv, qa[c]);     // FFMA-imm
                    if (m == i) acc[i] = cand;
                    else acc[i] = ISMAX ? fmaxf(acc[i], cand) : fminf(acc[i], cand);
                }
            }
        }
    }

    float* d = dst + (size_t)img * PIMG + (size_t)(32u + r) * PSTR + 32u + p0;
#pragma unroll
    for (int i = 0; i < T; i += 4)
        *reinterpret_cast<float4*>(d + i) = make_float4(acc[i], acc[i+1], acc[i+2], acc[i+3]);
}

// ---------------- vertical pass: T rows x 4 cols per thread ------------------
template <int W, int T, bool ISMAX>
__device__ __forceinline__ void vscale(unsigned t, const float* __restrict__ src,
                                       float* __restrict__ dst,
                                       unsigned dRowStride, unsigned dImgStride, float coef)
{
    constexpr unsigned NRG = 256 / T;
    unsigned colg = t & 63u;
    unsigned c0 = colg * 4u;
    unsigned rowg = (t >> 6) & (NRG - 1u);
    unsigned img = t / (64u * NRG);
    unsigned r0 = rowg * T;
    const float* s = src + (size_t)img * PIMG
                         + (size_t)(32u + r0 - W) * PSTR + 32u + c0;

    float4 acc[T];
#pragma unroll
    for (int m = 0; m < T + 2 * W; m++) {
        float4 q = __ldg(reinterpret_cast<const float4*>(s + (size_t)m * PSTR));
#pragma unroll
        for (int i = 0; i < T; i++) {
            if (m >= i && m <= i + 2 * W) {
                float wv = ISMAX ? -sew<W>(m - W - i) : sew<W>(m - W - i);
                float4 cd;
                cd.x = fmaf(coef, wv, q.x);
                cd.y = fmaf(coef, wv, q.y);
                cd.z = fmaf(coef, wv, q.z);
                cd.w = fmaf(coef, wv, q.w);
                if (m == i) {
                    acc[i] = cd;
                } else if (ISMAX) {
                    acc[i].x = fmaxf(acc[i].x, cd.x);
                    acc[i].y = fmaxf(acc[i].y, cd.y);
                    acc[i].z = fmaxf(acc[i].z, cd.z);
                    acc[i].w = fmaxf(acc[i].w, cd.w);
                } else {
                    acc[i].x = fminf(acc[i].x, cd.x);
                    acc[i].y = fminf(acc[i].y, cd.y);
                    acc[i].z = fminf(acc[i].z, cd.z);
                    acc[i].w = fminf(acc[i].w, cd.w);
                }
            }
        }
    }

    float* d = dst + (size_t)img * dImgStride + (size_t)r0 * dRowStride + c0;
#pragma unroll
    for (int i = 0; i < T; i++)
        *reinterpret_cast<float4*>(d + (size_t)i * dRowStride) = acc[i];
}

// ---------------- pass kernels (flat block ranges per scale) ----------------
// H passes: s0 [0,1024) W4 T8 | s1 [1024,2048) W8 T8 | s2 [2048,3072) W16 T8 | s3 [3072,5120) W32 T4
// V passes: s0 [0,256)  W4 T8 | s1 [256,512)  W8 T8 | s2 [512,768)  W16 T8 | s3 [768,1280)  W32 T4

__global__ void __launch_bounds__(256) k_hdil(const float* __restrict__ coefp)
{
    float coef = __ldg(coefp);
    unsigned bx = blockIdx.x, tx = threadIdx.x;
    if (bx < 1024u)      hscale<4, 8, true>( bx          * 256u + tx, g_inpad, (unsigned)INIMG, 0u, g_s1 + 0 * PSLAB, coef);
    else if (bx < 2048u) hscale<8, 8, true>((bx - 1024u) * 256u + tx, g_inpad, (unsigned)INIMG, 0u, g_s1 + 1 * PSLAB, coef);
    else if (bx < 3072u) hscale<16, 8, true>((bx - 2048u) * 256u + tx, g_inpad, (unsigned)INIMG, 0u, g_s1 + 2 * PSLAB, coef);
    else                 hscale<32, 4, true>((bx - 3072u) * 256u + tx, g_inpad, (unsigned)INIMG, 0u, g_s1 + 3 * PSLAB, coef);
}

__global__ void __launch_bounds__(256) k_vdil(const float* __restrict__ coefp)
{
    float coef = __ldg(coefp);
    unsigned bx = blockIdx.x, tx = threadIdx.x;
    // dst = s2 interior origin (row 32, col 32)
    if (bx < 256u)       vscale<4, 8, true>( bx         * 256u + tx, g_s1 + 0 * PSLAB, g_s2 + 0 * PSLAB + 32u * PSTR + 32u, PSTR, (unsigned)PIMG, coef);
    else if (bx < 512u)  vscale<8, 8, true>((bx - 256u) * 256u + tx, g_s1 + 1 * PSLAB, g_s2 + 1 * PSLAB + 32u * PSTR + 32u, PSTR, (unsigned)PIMG, coef);
    else if (bx < 768u)  vscale<16, 8, true>((bx - 512u) * 256u + tx, g_s1 + 2 * PSLAB, g_s2 + 2 * PSLAB + 32u * PSTR + 32u, PSTR, (unsigned)PIMG, coef);
    else                 vscale<32, 4, true>((bx - 768u) * 256u + tx, g_s1 + 3 * PSLAB, g_s2 + 3 * PSLAB + 32u * PSTR + 32u, PSTR, (unsigned)PIMG, coef);
}

__global__ void __launch_bounds__(256) k_hero(const float* __restrict__ coefp)
{
    float coef = __ldg(coefp);
    unsigned bx = blockIdx.x, tx = threadIdx.x;
    if (bx < 1024u)      hscale<4, 8, false>( bx          * 256u + tx, g_s2 + 0 * PSLAB, (unsigned)PIMG, 32u, g_s3 + 0 * PSLAB, coef);
    else if (bx < 2048u) hscale<8, 8, false>((bx - 1024u) * 256u + tx, g_s2 + 1 * PSLAB, (unsigned)PIMG, 32u, g_s3 + 1 * PSLAB, coef);
    else if (bx < 3072u) hscale<16, 8, false>((bx - 2048u) * 256u + tx, g_s2 + 2 * PSLAB, (unsigned)PIMG, 32u, g_s3 + 2 * PSLAB, coef);
    else                 hscale<32, 4, false>((bx - 3072u) * 256u + tx, g_s2 + 3 * PSLAB, (unsigned)PIMG, 32u, g_s3 + 3 * PSLAB, coef);
}

__global__ void __launch_bounds__(256) k_vero(float* __restrict__ out,
                                              const float* __restrict__ coefp)
{
    float coef = __ldg(coefp);
    unsigned bx = blockIdx.x, tx = threadIdx.x;
    // out layout: [img][scale][256][256]; img stride 4*65536, scale stride 65536
    if (bx < 256u)       vscale<4, 8, false>( bx         * 256u + tx, g_s3 + 0 * PSLAB, out + 0u * 65536u, 256u, 262144u, coef);
    else if (bx < 512u)  vscale<8, 8, false>((bx - 256u) * 256u + tx, g_s3 + 1 * PSLAB, out + 1u * 65536u, 256u, 262144u, coef);
    else if (bx < 768u)  vscale<16, 8, false>((bx - 512u) * 256u + tx, g_s3 + 2 * PSLAB, out + 2u * 65536u, 256u, 262144u, coef);
    else                 vscale<32, 4, false>((bx - 768u) * 256u + tx, g_s3 + 3 * PSLAB, out + 3u * 65536u, 256u, 262144u, coef);
}

extern "C" void kernel_launch(void* const* d_in, const int* in_sizes, int n_in,
                              void* d_out, int out_size)
{
    const float* in   = (const float*)d_in[0];
    const float* coef = (const float*)d_in[1];
    float* out        = (float*)d_out;

    dim3 gprep(2560, 4);
    k_prep<<<gprep, 256>>>(in);            // padded input + constant halos
    k_hdil<<<5120, 256>>>(coef);           // H dilate: in_pad -> s1
    k_vdil<<<1280, 256>>>(coef);           // V dilate: s1 -> s2
    k_hero<<<5120, 256>>>(coef);           // H erode : s2 -> s3
    k_vero<<<1280, 256>>>(out, coef);      // V erode : s3 -> out
}

// round 4
// speedup vs baseline: 1.4837x; 1.0151x over previous
#include <cuda_runtime.h>
#include <math.h>

// ---------------------------------------------------------------------------
// Multi-scale morphological closing, [4,8,256,256] -> [4,8,4,256,256]
// closing_k = Vero(Hero(Vdil(Hdil(x)))), parabolic SE, W_k in {4,8,16,32},
// se(x) = x^2 * 4/W^2 (exact fp32), candidate = fmaf(coef, -/+se, v).
// Tight per-scale scratch: s1/s3 row-halo only (stride 256), s2 col-halo only
// (stride 256+2W). Live set/pass ~75MB -> L2 resident. T=8 outputs/thread
// everywhere, rolling accumulation, heavy scales scheduled first.
// ---------------------------------------------------------------------------

static constexpr float PADV = 10000.0f;

// per-scale geometry (k: W = 4,8,16,32); constexpr FUNCTIONS (device-legal)
__host__ __device__ constexpr unsigned WK(int k)  { return 4u << k; }
__host__ __device__ constexpr unsigned HSf(int k) { return 256u + 2u * WK(k); }     // 264,272,288,320
__host__ __device__ constexpr unsigned SZf(int k) { return 256u * HSf(k); }         // per-image floats
__host__ __device__ constexpr size_t  OFFf(int k) {
    return (k == 0) ? 0u
         : (k == 1) ? (size_t)32u * SZf(0)
         : (k == 2) ? (size_t)32u * (SZf(0) + SZf(1))
                    : (size_t)32u * (SZf(0) + SZf(1) + SZf(2));
}
static constexpr size_t TOT = (size_t)32u * (SZf(0) + SZf(1) + SZf(2) + SZf(3));    // 9,371,648

__device__ float g_inpad[320u * 256u * 32u];   // 10.5 MB, col-halo 32, -PADV
__device__ float g_s1[TOT];                    // 37.5 MB, row-halo -PADV
__device__ float g_s2[TOT];                    // 37.5 MB, col-halo +PADV
__device__ float g_s3[TOT];                    // 37.5 MB, row-halo +PADV

template <int W>
__device__ __forceinline__ constexpr float sew(int x) {
    return (float)(x * x) * (4.0f / (float)(W * W));   // exact in fp32
}

// ---------------- prep: padded input + constant halos ----------------
__global__ void __launch_bounds__(256) k_prep(const float* __restrict__ in)
{
    unsigned f = blockIdx.x * 256u + threadIdx.x;
    unsigned task = blockIdx.y;
    const float4 neg = make_float4(-PADV, -PADV, -PADV, -PADV);
    const float4 pos = make_float4( PADV,  PADV,  PADV,  PADV);

    if (task == 0u) {                        // in_pad: 32 img * 256 rows * 80 f4
        if (f >= 655360u) return;
        unsigned img = f / 20480u, rem = f % 20480u;
        unsigned row = rem / 80u, c4 = rem % 80u;
        float4* d = reinterpret_cast<float4*>(g_inpad) + img * 20480u + row * 80u + c4;
        if (c4 >= 8u && c4 < 72u) {
            *d = __ldg(reinterpret_cast<const float4*>(in) + img * 16384u + row * 64u + (c4 - 8u));
        } else *d = neg;
        return;
    }
    // tasks 1/3: s1/s3 row halos (2W rows * 64 f4 per img-scale)
    // task  2  : s2 col halos (256 rows * (W/2) f4 per img-scale)
    // per-scale f4 totals: {16384, 32768, 65536, 131072}, cumulative below
    if (f >= 245760u) return;
    int k; unsigned base;
    if (f < 16384u)       { k = 0; base = 0u; }
    else if (f < 49152u)  { k = 1; base = 16384u; }
    else if (f < 114688u) { k = 2; base = 49152u; }
    else                  { k = 3; base = 114688u; }
    unsigned W = WK(k);
    unsigned local = f - base;
    unsigned HS = HSf(k), SZ = SZf(k);
    size_t OFF = OFFf(k);

    if (task == 1u || task == 3u) {          // row halos
        unsigned perImg = 2u * W * 64u;
        unsigned img = local / perImg, rem = local % perImg;
        unsigned rowIdx = rem / 64u, c4 = rem % 64u;
        unsigned row = (rowIdx < W) ? rowIdx : (256u + rowIdx);
        float* buf = (task == 1u) ? g_s1 : g_s3;
        float4* d = reinterpret_cast<float4*>(buf + OFF + (size_t)img * SZ) + row * 64u + c4;
        *d = (task == 1u) ? neg : pos;
    } else {                                 // s2 col halos
        unsigned f4pr = W / 2u;              // f4 per row (2W floats)
        unsigned perImg = 256u * f4pr;
        unsigned img = local / perImg, rem = local % perImg;
        unsigned row = rem / f4pr, kk = rem % f4pr;
        unsigned c4 = (kk < W / 4u) ? kk : (64u + kk - W / 4u + (256u + W) / 4u - 64u);
        // left halo f4 indices [0, W/4), right halo starts at float col 256+W -> f4 (256+W)/4
        c4 = (kk < W / 4u) ? kk : ((256u + W) / 4u + (kk - W / 4u));
        float4* d = reinterpret_cast<float4*>(g_s2 + OFF + (size_t)img * SZ) + row * (HS / 4u) + c4;
        *d = pos;
    }
}

// ---------------- horizontal pass: 8 contiguous outputs/thread --------------
// src pre-offset so load addr = src + img*sIS + r*sRS + p0 (16B aligned)
template <int W, bool ISMAX>
__device__ __forceinline__ void hpass(unsigned t, const float* __restrict__ src,
                                      unsigned sIS, unsigned sRS,
                                      float* __restrict__ dst, unsigned dIS, float coef)
{
    unsigned grp = t & 31u, row = t >> 5;
    unsigned img = row >> 8, r = row & 255u;
    unsigned p0 = grp * 8u;
    const float4* s = reinterpret_cast<const float4*>(src + (size_t)img * sIS + (size_t)r * sRS + p0);

    float acc[8];
    constexpr int NLD = (8 + 2 * W) / 4;
#pragma unroll
    for (int v = 0; v < NLD; v++) {
        float4 q = __ldg(s + v);
        float qa[4] = {q.x, q.y, q.z, q.w};
#pragma unroll
        for (int c = 0; c < 4; c++) {
            int m = 4 * v + c;
#pragma unroll
            for (int i = 0; i < 8; i++) {
                if (m >= i && m <= i + 2 * W) {
                    float wv = ISMAX ? -sew<W>(m - W - i) : sew<W>(m - W - i);
                    float cand = fmaf(coef, wv, qa[c]);     // FFMA-imm
                    if (m == i) acc[i] = cand;
                    else acc[i] = ISMAX ? fmaxf(acc[i], cand) : fminf(acc[i], cand);
                }
            }
        }
    }
    float* d = dst + (size_t)img * dIS + (size_t)r * 256u + p0;
    *reinterpret_cast<float4*>(d)     = make_float4(acc[0], acc[1], acc[2], acc[3]);
    *reinterpret_cast<float4*>(d + 4) = make_float4(acc[4], acc[5], acc[6], acc[7]);
}

// ---------------- vertical pass: 8 rows x 4 cols per thread ------------------
// src: stride 256, window starts at buffer row r0. dst pre-offset to interior.
template <int W, bool ISMAX>
__device__ __forceinline__ void vpass(unsigned t, const float* __restrict__ src,
                                      unsigned sIS, float* __restrict__ dst,
                                      unsigned dIS, unsigned dRS, float coef)
{
    unsigned colg = t & 63u, rowg = (t >> 6) & 31u, img = t >> 11;
    unsigned c0 = colg * 4u, r0 = rowg * 8u;
    const float* s = src + (size_t)img * sIS + (size_t)r0 * 256u + c0;

    float4 acc[8];
#pragma unroll
    for (int m = 0; m < 8 + 2 * W; m++) {
        float4 q = __ldg(reinterpret_cast<const float4*>(s + (size_t)m * 256u));
#pragma unroll
        for (int i = 0; i < 8; i++) {
            if (m >= i && m <= i + 2 * W) {
                float wv = ISMAX ? -sew<W>(m - W - i) : sew<W>(m - W - i);
                float4 cd;
                cd.x = fmaf(coef, wv, q.x);
                cd.y = fmaf(coef, wv, q.y);
                cd.z = fmaf(coef, wv, q.z);
                cd.w = fmaf(coef, wv, q.w);
                if (m == i) acc[i] = cd;
                else if (ISMAX) {
                    acc[i].x = fmaxf(acc[i].x, cd.x); acc[i].y = fmaxf(acc[i].y, cd.y);
                    acc[i].z = fmaxf(acc[i].z, cd.z); acc[i].w = fmaxf(acc[i].w, cd.w);
                } else {
                    acc[i].x = fminf(acc[i].x, cd.x); acc[i].y = fminf(acc[i].y, cd.y);
                    acc[i].z = fminf(acc[i].z, cd.z); acc[i].w = fminf(acc[i].w, cd.w);
                }
            }
        }
    }
    float* d = dst + (size_t)img * dIS + (size_t)r0 * dRS + c0;
#pragma unroll
    for (int i = 0; i < 8; i++)
        *reinterpret_cast<float4*>(d + (size_t)i * dRS) = acc[i];
}

// ---------------- pass kernels: heavy scales (W32) scheduled first ----------
// H kernels: 4096 blocks (1024/scale). V kernels: 1024 blocks (256/scale).

__global__ void __launch_bounds__(256) k_hdil(const float* __restrict__ coefp)
{
    float coef = __ldg(coefp);
    unsigned bx = blockIdx.x, tx = threadIdx.x;
    if (bx < 1024u)      hpass<32, true>( bx          * 256u + tx, g_inpad + 0,  81920u, 320u, g_s1 + OFFf(3) + 32u * 256u, SZf(3), coef);
    else if (bx < 2048u) hpass<16, true>((bx - 1024u) * 256u + tx, g_inpad + 16, 81920u, 320u, g_s1 + OFFf(2) + 16u * 256u, SZf(2), coef);
    else if (bx < 3072u) hpass<8,  true>((bx - 2048u) * 256u + tx, g_inpad + 24, 81920u, 320u, g_s1 + OFFf(1) +  8u * 256u, SZf(1), coef);
    else                 hpass<4,  true>((bx - 3072u) * 256u + tx, g_inpad + 28, 81920u, 320u, g_s1 + OFFf(0) +  4u * 256u, SZf(0), coef);
}

__global__ void __launch_bounds__(256) k_vdil(const float* __restrict__ coefp)
{
    float coef = __ldg(coefp);
    unsigned bx = blockIdx.x, tx = threadIdx.x;
    if (bx < 256u)       vpass<32, true>( bx         * 256u + tx, g_s1 + OFFf(3), SZf(3), g_s2 + OFFf(3) + 32u, SZf(3), HSf(3), coef);
    else if (bx < 512u)  vpass<16, true>((bx - 256u) * 256u + tx, g_s1 + OFFf(2), SZf(2), g_s2 + OFFf(2) + 16u, SZf(2), HSf(2), coef);
    else if (bx < 768u)  vpass<8,  true>((bx - 512u) * 256u + tx, g_s1 + OFFf(1), SZf(1), g_s2 + OFFf(1) +  8u, SZf(1), HSf(1), coef);
    else                 vpass<4,  true>((bx - 768u) * 256u + tx, g_s1 + OFFf(0), SZf(0), g_s2 + OFFf(0) +  4u, SZf(0), HSf(0), coef);
}

__global__ void __launch_bounds__(256) k_hero(const float* __restrict__ coefp)
{
    float coef = __ldg(coefp);
    unsigned bx = blockIdx.x, tx = threadIdx.x;
    if (bx < 1024u)      hpass<32, false>( bx          * 256u + tx, g_s2 + OFFf(3), SZf(3), HSf(3), g_s3 + OFFf(3) + 32u * 256u, SZf(3), coef);
    else if (bx < 2048u) hpass<16, false>((bx - 1024u) * 256u + tx, g_s2 + OFFf(2), SZf(2), HSf(2), g_s3 + OFFf(2) + 16u * 256u, SZf(2), coef);
    else if (bx < 3072u) hpass<8,  false>((bx - 2048u) * 256u + tx, g_s2 + OFFf(1), SZf(1), HSf(1), g_s3 + OFFf(1) +  8u * 256u, SZf(1), coef);
    else                 hpass<4,  false>((bx - 3072u) * 256u + tx, g_s2 + OFFf(0), SZf(0), HSf(0), g_s3 + OFFf(0) +  4u * 256u, SZf(0), coef);
}

__global__ void __launch_bounds__(256) k_vero(float* __restrict__ out,
                                              const float* __restrict__ coefp)
{
    float coef = __ldg(coefp);
    unsigned bx = blockIdx.x, tx = threadIdx.x;
    // out: [img][scale][256][256], img stride 262144, scale stride 65536
    if (bx < 256u)       vpass<32, false>( bx         * 256u + tx, g_s3 + OFFf(3), SZf(3), out + 3u * 65536u, 262144u, 256u, coef);
    else if (bx < 512u)  vpass<16, false>((bx - 256u) * 256u + tx, g_s3 + OFFf(2), SZf(2), out + 2u * 65536u, 262144u, 256u, coef);
    else if (bx < 768u)  vpass<8,  false>((bx - 512u) * 256u + tx, g_s3 + OFFf(1), SZf(1), out + 1u * 65536u, 262144u, 256u, coef);
    else                 vpass<4,  false>((bx - 768u) * 256u + tx, g_s3 + OFFf(0), SZf(0), out + 0u * 65536u, 262144u, 256u, coef);
}

extern "C" void kernel_launch(void* const* d_in, const int* in_sizes, int n_in,
                              void* d_out, int out_size)
{
    const float* in   = (const float*)d_in[0];
    const float* coef = (const float*)d_in[1];
    float* out        = (float*)d_out;

    dim3 gprep(2560, 4);
    k_prep<<<gprep, 256>>>(in);            // padded input + constant halos
    k_hdil<<<4096, 256>>>(coef);           // H dilate: in_pad -> s1
    k_vdil<<<1024, 256>>>(coef);           // V dilate: s1 -> s2
    k_hero<<<4096, 256>>>(coef);           // H erode : s2 -> s3
    k_vero<<<1024, 256>>>(out, coef);      // V erode : s3 -> out
}